// round 11
// baseline (speedup 1.0000x reference)
#include <cuda_runtime.h>

// MedianPool2d 3x3, stride 1, reflect pad (1,1,1,1)
// float32 [16, 3, 512, 512] -> same shape.
//
// R11 = R10 body with the register-repacking overhead removed:
//  - rows loaded as ulonglong2 so packed groups a=(c1,c2), b=(c3,c4) are
//    born as 64-bit pairs (no mov.b64 packing; halves aliased for SHFL)
//  - vertical stage: packed f32x2 arithmetic compare-exchange (FMA pipe)
//  - horizontal combine: scalar FMNMX (ALU pipe)
//  - halos via warp shuffle; single merged predicated lane-0/31 fixup
//  - 32-bit offsets, launch_bounds(128,12)

#define W 512
#define H 512

typedef unsigned long long u64;
typedef unsigned int u32;

__device__ __forceinline__ u64 pk(float x, float y) {
    u64 r; asm("mov.b64 %0, {%1, %2};" : "=l"(r) : "f"(x), "f"(y)); return r;
}
__device__ __forceinline__ float lo32(u64 v) {
    float a, b; asm("mov.b64 {%0, %1}, %2;" : "=f"(a), "=f"(b) : "l"(v)); return a;
}
__device__ __forceinline__ float hi32(u64 v) {
    float a, b; asm("mov.b64 {%0, %1}, %2;" : "=f"(a), "=f"(b) : "l"(v)); return b;
}
__device__ __forceinline__ float2 upk(u64 v) {
    float2 f; asm("mov.b64 {%0, %1}, %2;" : "=f"(f.x), "=f"(f.y) : "l"(v)); return f;
}

// packed compare-exchange on 2 fp32 lanes: lo=min, hi=max
__device__ __forceinline__ void cex2(u64 a, u64 b, u64& lo, u64& hi) {
    const u64 n1 = 0xBF800000BF800000ULL;
    const u64 hf = 0x3F0000003F000000ULL;
    const u64 nh = 0xBF000000BF000000ULL;
    u64 s, d, k, h;
    asm("add.rn.f32x2 %0, %1, %2;" : "=l"(s) : "l"(a), "l"(b));
    asm("fma.rn.f32x2 %0, %1, %2, %3;" : "=l"(d) : "l"(b), "l"(n1), "l"(a)); // a-b
    k = d & 0x7FFFFFFF7FFFFFFFULL;                                           // |a-b|
    asm("mul.rn.f32x2 %0, %1, %2;" : "=l"(h) : "l"(s), "l"(hf));             // 0.5(a+b)
    asm("fma.rn.f32x2 %0, %1, %2, %3;" : "=l"(lo) : "l"(k), "l"(nh), "l"(h));
    asm("fma.rn.f32x2 %0, %1, %2, %3;" : "=l"(hi) : "l"(k), "l"(hf), "l"(h));
}

__device__ __forceinline__ float med3(float a, float b, float c) {
    return fmaxf(fminf(a, b), fminf(fmaxf(a, b), c));
}

struct Row3 { u64 a, b, c; };   // packed columns (1,2) (3,4) (0,5)

__device__ __forceinline__ void emit_row(const Row3& pl, const Row3& ph,
                                         const Row3& t,
                                         float* __restrict__ dst) {
    float4 res;
    u64 loa, mia, hia, loc, mic, hic, tm;
    cex2(pl.a, t.a, loa, tm);
    cex2(ph.a, tm, mia, hia);
    cex2(pl.c, t.c, loc, tm);
    cex2(ph.c, tm, mic, hic);

    float2 la = upk(loa), lc = upk(loc);
    float2 ma = upk(mia), mc = upk(mic);
    float2 ha = upk(hia), hc = upk(hic);

    float sA  = fmaxf(la.x, la.y);
    float tA  = fminf(ha.x, ha.y);
    float q0A = fminf(ma.x, ma.y), q1A = fmaxf(ma.x, ma.y);

    u64 lob, mib, hib;
    cex2(pl.b, t.b, lob, tm);
    cex2(ph.b, tm, mib, hib);
    float2 lb = upk(lob), mb = upk(mib), hb = upk(hib);

    res.x = med3(fmaxf(lc.x, sA),
                 fmaxf(q0A, fminf(q1A, mc.x)),
                 fminf(hc.x, tA));
    res.y = med3(fmaxf(sA, lb.x),
                 fmaxf(q0A, fminf(q1A, mb.x)),
                 fminf(tA, hb.x));

    float sB  = fmaxf(lb.x, lb.y);
    float tB  = fminf(hb.x, hb.y);
    float q0B = fminf(mb.x, mb.y), q1B = fmaxf(mb.x, mb.y);

    res.z = med3(fmaxf(la.y, sB),
                 fmaxf(q0B, fminf(q1B, ma.y)),
                 fminf(ha.y, tB));
    res.w = med3(fmaxf(sB, lc.y),
                 fmaxf(q0B, fminf(q1B, mc.y)),
                 fminf(tB, hc.y));

    *reinterpret_cast<float4*>(dst) = res;
}

__global__ __launch_bounds__(128, 12)
void median3x3_kernel(const float* __restrict__ x, float* __restrict__ out) {
    const int tid   = threadIdx.x;        // 0..127
    const int lane  = tid & 31;
    const int h0    = blockIdx.x << 1;    // 2 output rows per block
    const u32 plane = blockIdx.y;         // 0..47
    const int w0    = tid << 2;

    const u32 base = plane * (u32)(H * W);

    // frame rows f0..f3 = input rows h0-1 .. h0+2 (reflected at edges)
    const u32 o1 = base + (u32)h0 * W;
    const u32 o2 = o1 + W;
    const u32 o0 = (h0 == 0)     ? o2 : o1 - W;   // reflect row -1 -> 1
    const u32 o3 = (h0 + 2 >= H) ? o1 : o2 + W;   // reflect row H -> H-2

    // 4 vector loads as u64 pairs: v.x = cols(1,2) ... wait: memory order is
    // (c1,c2,c3,c4) at w0 -> v.x = (c1,c2), v.y = (c3,c4). Born packed.
    ulonglong2 v0 = *reinterpret_cast<const ulonglong2*>(x + o0 + w0);
    ulonglong2 v1 = *reinterpret_cast<const ulonglong2*>(x + o1 + w0);
    ulonglong2 v2 = *reinterpret_cast<const ulonglong2*>(x + o2 + w0);
    ulonglong2 v3 = *reinterpret_cast<const ulonglong2*>(x + o3 + w0);

    // merged boundary fixup: lane 0 loads left-halo col, lane 31 right-halo
    // col (reflect folded into the address). One predicated block.
    float fx0, fx1, fx2, fx3;
    if ((lane == 0) | (lane == 31)) {
        const u32 col = (lane == 0)
            ? ((w0 == 0) ? 1u : (u32)(w0 - 1))
            : ((w0 + 4 == W) ? (u32)(W - 2) : (u32)(w0 + 4));
        fx0 = x[o0 + col];
        fx1 = x[o1 + col];
        fx2 = x[o2 + col];
        fx3 = x[o3 + col];
    }

    // halo exchange via shuffle on register halves (c4 = hi of v.y, c1 = lo of v.x)
    float l0 = __shfl_up_sync(0xffffffffu, hi32(v0.y), 1);
    float l1 = __shfl_up_sync(0xffffffffu, hi32(v1.y), 1);
    float l2 = __shfl_up_sync(0xffffffffu, hi32(v2.y), 1);
    float l3 = __shfl_up_sync(0xffffffffu, hi32(v3.y), 1);
    float e0 = __shfl_down_sync(0xffffffffu, lo32(v0.x), 1);
    float e1 = __shfl_down_sync(0xffffffffu, lo32(v1.x), 1);
    float e2 = __shfl_down_sync(0xffffffffu, lo32(v2.x), 1);
    float e3 = __shfl_down_sync(0xffffffffu, lo32(v3.x), 1);

    if (lane == 0)  { l0 = fx0; l1 = fx1; l2 = fx2; l3 = fx3; }
    if (lane == 31) { e0 = fx0; e1 = fx1; e2 = fx2; e3 = fx3; }

    Row3 f0, f1, f2, f3;
    f0.a = v0.x; f0.b = v0.y; f0.c = pk(l0, e0);
    f1.a = v1.x; f1.b = v1.y; f1.c = pk(l1, e1);
    f2.a = v2.x; f2.b = v2.y; f2.c = pk(l2, e2);
    f3.a = v3.x; f3.b = v3.y; f3.c = pk(l3, e3);

    // pair sort rows f1,f2 (both die afterward)
    Row3 pl, ph;
    cex2(f1.a, f2.a, pl.a, ph.a);
    cex2(f1.b, f2.b, pl.b, ph.b);
    cex2(f1.c, f2.c, pl.c, ph.c);

    float* o = out + o1 + w0;
    emit_row(pl, ph, f0, o);        // output row h0
    emit_row(pl, ph, f3, o + W);    // output row h0+1
}

extern "C" void kernel_launch(void* const* d_in, const int* in_sizes, int n_in,
                              void* d_out, int out_size) {
    const float* x = (const float*)d_in[0];
    float* out = (float*)d_out;
    dim3 grid(H / 2, 48);    // 256 row-pairs x 48 planes = 12288 blocks
    dim3 block(128);
    median3x3_kernel<<<grid, block>>>(x, out);
}